// round 5
// baseline (speedup 1.0000x reference)
#include <cuda_runtime.h>
#include <cuda_bf16.h>
#include <cstdint>

#define SQ 2048
#define EM 2048
#define NH 32
#define HD 64

// ---------------- device scratch (allocation-free rule) ----------------------
__device__ float g_Q[NH * SQ * HD];
__device__ float g_K[NH * SQ * HD];
__device__ float g_V[NH * SQ * HD];
__device__ float g_ctx[SQ * EM];
__device__ float g_scores[(size_t)NH * SQ * SQ];   // fallback only
__device__ float2 g_stats[NH * SQ];

__device__ __nv_bfloat16 g_hidH[SQ * EM], g_hidL[SQ * EM];
__device__ __nv_bfloat16 g_WqH[EM * EM],  g_WqL[EM * EM];
__device__ __nv_bfloat16 g_WkH[EM * EM],  g_WkL[EM * EM];
__device__ __nv_bfloat16 g_WvH[EM * EM],  g_WvL[EM * EM];
__device__ __nv_bfloat16 g_WoH[EM * EM],  g_WoL[EM * EM];
__device__ __nv_bfloat16 g_ctxH[SQ * EM], g_ctxL[SQ * EM];
// shaped [h][s][hd] hi/lo splits written by projection epilogues
__device__ __nv_bfloat16 g_QsH[NH * SQ * HD], g_QsL[NH * SQ * HD];
__device__ __nv_bfloat16 g_KsH[NH * SQ * HD], g_KsL[NH * SQ * HD];
__device__ __nv_bfloat16 g_VsH[NH * SQ * HD], g_VsL[NH * SQ * HD];

// ---------------- helpers ----------------------------------------------------
__device__ __forceinline__ uint32_t smem_u32(const void* p) {
    uint32_t a;
    asm("{ .reg .u64 t; cvta.to.shared.u64 t, %1; cvt.u32.u64 %0, t; }"
        : "=r"(a) : "l"(p));
    return a;
}
__device__ __forceinline__ void ldsm4(uint32_t* r, uint32_t addr) {
    asm volatile("ldmatrix.sync.aligned.m8n8.x4.shared.b16 {%0,%1,%2,%3}, [%4];"
                 : "=r"(r[0]), "=r"(r[1]), "=r"(r[2]), "=r"(r[3]) : "r"(addr));
}
__device__ __forceinline__ void ldsm4t(uint32_t* r, uint32_t addr) {
    asm volatile("ldmatrix.sync.aligned.m8n8.x4.trans.shared.b16 {%0,%1,%2,%3}, [%4];"
                 : "=r"(r[0]), "=r"(r[1]), "=r"(r[2]), "=r"(r[3]) : "r"(addr));
}
__device__ __forceinline__ void mma16816(float* c, const uint32_t* a,
                                         const uint32_t* b) {
    asm volatile(
        "mma.sync.aligned.m16n8k16.row.col.f32.bf16.bf16.f32 "
        "{%0,%1,%2,%3}, {%4,%5,%6,%7}, {%8,%9}, {%0,%1,%2,%3};"
        : "+f"(c[0]), "+f"(c[1]), "+f"(c[2]), "+f"(c[3])
        : "r"(a[0]), "r"(a[1]), "r"(a[2]), "r"(a[3]), "r"(b[0]), "r"(b[1]));
}
__device__ __forceinline__ uint32_t sw(uint32_t off) {
    return off ^ ((off >> 3) & 0x70);
}

// fp32 -> bf16 hi/lo split
__global__ void __launch_bounds__(256)
split_bf16(const float* __restrict__ x, __nv_bfloat16* __restrict__ hi,
           __nv_bfloat16* __restrict__ lo, int n)
{
    int i = (blockIdx.x * 256 + threadIdx.x) * 4;
    if (i >= n) return;
    float4 v = *(const float4*)(x + i);
    __nv_bfloat16 h[4], l[4];
    float vv[4] = {v.x, v.y, v.z, v.w};
#pragma unroll
    for (int j = 0; j < 4; j++) {
        h[j] = __float2bfloat16(vv[j]);
        l[j] = __float2bfloat16(vv[j] - __bfloat162float(h[j]));
    }
    *(uint2*)(hi + i) = *(const uint2*)h;
    *(uint2*)(lo + i) = *(const uint2*)l;
}

// ============================================================================
// Shared MMA stage over 4 operand tiles (Ah,Al,Bh,Bl), 128 rows x 128B each.
// ============================================================================
#define TILE_B 16384

__device__ __forceinline__ void
mma_stage(uint32_t base, int wm, int wn, int l, float acc[4][4][4])
{
    const uint32_t aH = base, aL = base + TILE_B;
    const uint32_t bH = base + 2 * TILE_B, bL = base + 3 * TILE_B;
#pragma unroll
    for (int ks = 0; ks < 4; ks++) {
        uint32_t ah[4][4], al[4][4], bh[4][2], bl[4][2];
#pragma unroll
        for (int mt = 0; mt < 4; mt++) {
            int row = wm * 64 + mt * 16 + (l & 15);
            int chk = ks * 2 + (l >> 4);
            uint32_t off = sw(row * 128 + chk * 16);
            ldsm4(ah[mt], aH + off);
            ldsm4(al[mt], aL + off);
        }
#pragma unroll
        for (int j = 0; j < 2; j++) {
            int row = wn * 32 + j * 16 + (l & 7) + ((l >> 4) << 3);
            int chk = ks * 2 + ((l >> 3) & 1);
            uint32_t off = sw(row * 128 + chk * 16);
            uint32_t t4[4];
            ldsm4(t4, bH + off);
            bh[2 * j][0] = t4[0]; bh[2 * j][1] = t4[1];
            bh[2 * j + 1][0] = t4[2]; bh[2 * j + 1][1] = t4[3];
            ldsm4(t4, bL + off);
            bl[2 * j][0] = t4[0]; bl[2 * j][1] = t4[1];
            bl[2 * j + 1][0] = t4[2]; bl[2 * j + 1][1] = t4[3];
        }
#pragma unroll
        for (int mt = 0; mt < 4; mt++)
#pragma unroll
            for (int nt = 0; nt < 4; nt++) {
                mma16816(acc[mt][nt], ah[mt], bh[nt]);
                mma16816(acc[mt][nt], ah[mt], bl[nt]);
                mma16816(acc[mt][nt], al[mt], bh[nt]);
            }
    }
}

// ============================================================================
// Tensor-core split-bf16 GEMM: C = (A @ B^T + bias) * scale, 2048^3.
// ============================================================================
#define SMEM_SZ (8 * TILE_B)

template <int MODE, bool SPLIT>
__global__ void __launch_bounds__(256)
mma_gemm(const __nv_bfloat16* __restrict__ Ah, const __nv_bfloat16* __restrict__ Al,
         const __nv_bfloat16* __restrict__ Bh, const __nv_bfloat16* __restrict__ Bl,
         const float* __restrict__ bias, float* __restrict__ C,
         __nv_bfloat16* __restrict__ Chi, __nv_bfloat16* __restrict__ Clo,
         float scale)
{
    extern __shared__ char smem[];
    const uint32_t sb = smem_u32(smem);
    const int tid = threadIdx.x;
    const int w = tid >> 5, l = tid & 31;
    const int wm = w >> 2, wn = w & 3;
    const int m0 = blockIdx.y * 128;
    const int n0 = blockIdx.x * 128;

    auto issue = [&](int s, int k0) {
#pragma unroll
        for (int it = 0; it < 16; it++) {
            int c = tid + it * 256;
            int o = c >> 10;
            int row = (c >> 3) & 127;
            int chk = c & 7;
            const __nv_bfloat16* p = (o == 0) ? Ah : (o == 1) ? Al
                                   : (o == 2) ? Bh : Bl;
            int rb = (o < 2) ? m0 : n0;
            const void* g = p + (size_t)(rb + row) * 2048 + k0 + chk * 8;
            uint32_t d = sb + (uint32_t)(s * 4 + o) * TILE_B
                         + sw(row * 128 + chk * 16);
            asm volatile("cp.async.cg.shared.global [%0], [%1], 16;\n"
                         :: "r"(d), "l"(g));
        }
        asm volatile("cp.async.commit_group;\n" ::: "memory");
    };

    float acc[4][4][4] = {};
    issue(0, 0);

    const int NS = 2048 / 64;
    for (int i = 0; i < NS; i++) {
        if (i + 1 < NS) {
            issue((i + 1) & 1, (i + 1) * 64);
            asm volatile("cp.async.wait_group 1;\n" ::: "memory");
        } else {
            asm volatile("cp.async.wait_group 0;\n" ::: "memory");
        }
        __syncthreads();
        mma_stage(sb + (uint32_t)((i & 1) * 4) * TILE_B, wm, wn, l, acc);
        __syncthreads();
    }

#pragma unroll
    for (int mt = 0; mt < 4; mt++) {
#pragma unroll
        for (int nt = 0; nt < 4; nt++) {
            int m = m0 + wm * 64 + mt * 16 + (l >> 2);
            int n = n0 + wn * 32 + nt * 8 + (l & 3) * 2;
#pragma unroll
            for (int hf = 0; hf < 2; hf++) {
                int row = m + hf * 8;
                float v0 = (acc[mt][nt][hf * 2 + 0] + bias[n]) * scale;
                float v1 = (acc[mt][nt][hf * 2 + 1] + bias[n + 1]) * scale;
                size_t idx;
                if (MODE == 0)
                    idx = (size_t)row * 2048 + n;
                else
                    idx = (((size_t)(n >> 6)) * SQ + row) * HD + (n & 63);
                C[idx] = v0;
                C[idx + 1] = v1;
                if (SPLIT) {
                    __nv_bfloat16 h0 = __float2bfloat16(v0);
                    __nv_bfloat16 h1 = __float2bfloat16(v1);
                    __nv_bfloat16 l0 = __float2bfloat16(v0 - __bfloat162float(h0));
                    __nv_bfloat16 l1 = __float2bfloat16(v1 - __bfloat162float(h1));
                    Chi[idx] = h0; Chi[idx + 1] = h1;
                    Clo[idx] = l0; Clo[idx + 1] = l1;
                }
            }
        }
    }
}

// ============================================================================
// Tensor-core scores: scores[h] = Qs @ Ks^T per head, K=64 (one stage).
// ============================================================================
#define SC_SMEM (4 * TILE_B)

__global__ void __launch_bounds__(256)
scores_mma(const __nv_bfloat16* __restrict__ Qh, const __nv_bfloat16* __restrict__ Ql,
           const __nv_bfloat16* __restrict__ Kh, const __nv_bfloat16* __restrict__ Kl,
           float* __restrict__ scores)
{
    if (blockIdx.x > blockIdx.y) return;
    extern __shared__ char smem[];
    const uint32_t sb = smem_u32(smem);
    const int tid = threadIdx.x;
    const int w = tid >> 5, l = tid & 31;
    const int wm = w >> 2, wn = w & 3;
    const int h  = blockIdx.z;
    const int q0 = blockIdx.y * 128;
    const int k0 = blockIdx.x * 128;
    const size_t hb = (size_t)h * SQ * HD;

#pragma unroll
    for (int it = 0; it < 16; it++) {
        int c = tid + it * 256;
        int o = c >> 10;
        int row = (c >> 3) & 127;
        int chk = c & 7;
        const __nv_bfloat16* p = (o == 0) ? Qh : (o == 1) ? Ql
                               : (o == 2) ? Kh : Kl;
        int rb = (o < 2) ? q0 : k0;
        const void* g = p + hb + (size_t)(rb + row) * HD + chk * 8;
        uint32_t d = sb + (uint32_t)o * TILE_B + sw(row * 128 + chk * 16);
        asm volatile("cp.async.cg.shared.global [%0], [%1], 16;\n"
                     :: "r"(d), "l"(g));
    }
    asm volatile("cp.async.commit_group;\n" ::: "memory");
    asm volatile("cp.async.wait_group 0;\n" ::: "memory");
    __syncthreads();

    float acc[4][4][4] = {};
    mma_stage(sb, wm, wn, l, acc);

    float* Co = scores + (size_t)h * SQ * SQ;
#pragma unroll
    for (int mt = 0; mt < 4; mt++)
#pragma unroll
        for (int nt = 0; nt < 4; nt++) {
            int m = q0 + wm * 64 + mt * 16 + (l >> 2);
            int n = k0 + wn * 32 + nt * 8 + (l & 3) * 2;
#pragma unroll
            for (int hf = 0; hf < 2; hf++) {
                size_t idx = (size_t)(m + hf * 8) * SQ + n;
                Co[idx]     = acc[mt][nt][hf * 2 + 0];
                Co[idx + 1] = acc[mt][nt][hf * 2 + 1];
            }
        }
}

// ============================================================================
// Row stats (max, 1/sum of exp) over the causal part of each raw-score row,
// plus zero-fill of the strictly-above-diagonal-block region of the weights.
// ============================================================================
__global__ void __launch_bounds__(256)
rowstats_zero(float* __restrict__ scores, float2* __restrict__ stats)
{
    const int q = blockIdx.x;
    const int h = blockIdx.y;
    const int t = threadIdx.x;
    float* row = scores + ((size_t)h * SQ + q) * SQ;

    const float NEG_INF = __int_as_float(0xff800000);
    float mx = NEG_INF;
    for (int k = t; k <= q; k += 256) mx = fmaxf(mx, row[k]);

    __shared__ float red[256];
    red[t] = mx; __syncthreads();
    for (int s2 = 128; s2 > 0; s2 >>= 1) {
        if (t < s2) red[t] = fmaxf(red[t], red[t + s2]);
        __syncthreads();
    }
    mx = red[0]; __syncthreads();

    float sum = 0.0f;
    for (int k = t; k <= q; k += 256) sum += __expf(row[k] - mx);
    red[t] = sum; __syncthreads();
    for (int s2 = 128; s2 > 0; s2 >>= 1) {
        if (t < s2) red[t] += red[t + s2];
        __syncthreads();
    }
    if (t == 0) stats[h * SQ + q] = make_float2(mx, 1.0f / red[0]);

    // zero region above this row's diagonal 128-tile
    const int kstart = ((q >> 7) + 1) << 7;
    const float4 z = make_float4(0.f, 0.f, 0.f, 0.f);
    for (int k = kstart + t * 4; k < SQ; k += 1024)
        *(float4*)(row + k) = z;
}

// ============================================================================
// Fused: normalize weights (in place) + ctx = W @ V via tensor cores.
// Grid (16 qtiles reversed, NH). Smem: A hi/lo [2][128][64]b16 + V hi/lo tiles.
// ============================================================================
#define FA_AH 0
#define FA_AL 32768
#define FA_VH 65536
#define FA_VL 81920
#define FA_SMEM 98304

__global__ void __launch_bounds__(256)
fused_wv(float* __restrict__ weights,
         const __nv_bfloat16* __restrict__ VsH, const __nv_bfloat16* __restrict__ VsL,
         const float2* __restrict__ stats, float* __restrict__ ctx)
{
    extern __shared__ char smem[];
    const uint32_t sb = smem_u32(smem);
    char* smc = smem;
    const int tid = threadIdx.x;
    const int w = tid >> 5, l = tid & 31;
    const int wm = w >> 2, wn = w & 3;
    const int h  = blockIdx.y;
    const int qt = 15 - blockIdx.x;          // big tiles first
    const int q0 = qt * 128;
    float* Wp = weights + (size_t)h * SQ * SQ;
    const size_t vb = (size_t)h * SQ * HD;

    const int qloc = tid >> 1;
    const int kh   = tid & 1;
    const int qg   = q0 + qloc;
    const float2 st = stats[h * SQ + qg];
    const float mx = st.x, inv = st.y;

    float acc[4][2][4] = {};

    for (int k0 = 0; k0 <= q0; k0 += 128) {
        // V hi/lo tiles: 128 rows x 128B each
#pragma unroll
        for (int it = 0; it < 8; it++) {
            int c = tid + it * 256;
            int op = c >> 10;
            int row = (c >> 3) & 127;
            int chk = c & 7;
            const __nv_bfloat16* p = op ? VsL : VsH;
            const void* g = p + vb + (size_t)(k0 + row) * HD + chk * 8;
            uint32_t d = sb + (op ? FA_VL : FA_VH) + sw(row * 128 + chk * 16);
            asm volatile("cp.async.cg.shared.global [%0], [%1], 16;\n"
                         :: "r"(d), "l"(g));
        }
        asm volatile("cp.async.commit_group;\n" ::: "memory");

        // raw scores -> normalized weights (in place) + bf16 hi/lo to smem
        float* rowp = Wp + (size_t)qg * SQ + k0 + kh * 64;
        char* ahp = smc + FA_AH + kh * TILE_B;
        char* alp = smc + FA_AL + kh * TILE_B;
#pragma unroll
        for (int j = 0; j < 16; j++) {
            float4 s4 = *(const float4*)(rowp + j * 4);
            float sv[4] = {s4.x, s4.y, s4.z, s4.w};
            float wv[4];
#pragma unroll
            for (int e = 0; e < 4; e++) {
                int kg = k0 + kh * 64 + j * 4 + e;
                wv[e] = (kg <= qg) ? __expf(sv[e] - mx) * inv : 0.0f;
            }
            *(float4*)(rowp + j * 4) = make_float4(wv[0], wv[1], wv[2], wv[3]);
#pragma unroll
            for (int pr = 0; pr < 2; pr++) {
                float a0 = wv[pr * 2], a1 = wv[pr * 2 + 1];
                __nv_bfloat16 h0 = __float2bfloat16(a0);
                __nv_bfloat16 h1 = __float2bfloat16(a1);
                __nv_bfloat16 l0 = __float2bfloat16(a0 - __bfloat162float(h0));
                __nv_bfloat16 l1 = __float2bfloat16(a1 - __bfloat162float(h1));
                int kkl = j * 4 + pr * 2;                 // 0..62 within half
                uint32_t off = sw((uint32_t)(qloc * 128 + kkl * 2));
                uint32_t hp = ((uint32_t)__bfloat16_as_ushort(h1) << 16)
                              | __bfloat16_as_ushort(h0);
                uint32_t lp = ((uint32_t)__bfloat16_as_ushort(l1) << 16)
                              | __bfloat16_as_ushort(l0);
                *(uint32_t*)(ahp + off) = hp;
                *(uint32_t*)(alp + off) = lp;
            }
        }

        asm volatile("cp.async.wait_group 0;\n" ::: "memory");
        __syncthreads();

#pragma unroll
        for (int ks = 0; ks < 8; ks++) {
            int half = ks >> 2, ksl = ks & 3;
            uint32_t ah[4][4], al[4][4];
#pragma unroll
            for (int mt = 0; mt < 4; mt++) {
                int rowq = wm * 64 + mt * 16 + (l & 15);
                int chk = ksl * 2 + (l >> 4);
                uint32_t off = sw(rowq * 128 + chk * 16);
                ldsm4(ah[mt], sb + FA_AH + half * TILE_B + off);
                ldsm4(al[mt], sb + FA_AL + half * TILE_B + off);
            }
            uint32_t bh[4], bl[4];
            {
                int rowk = ks * 16 + (l & 15);
                int colb = wn * 32 + (l >> 4) * 16;
                uint32_t off = sw(rowk * 128 + colb);
                ldsm4t(bh, sb + FA_VH + off);
                ldsm4t(bl, sb + FA_VL + off);
            }
#pragma unroll
            for (int mt = 0; mt < 4; mt++)
#pragma unroll
                for (int nt = 0; nt < 2; nt++) {
                    mma16816(acc[mt][nt], ah[mt], bh + 2 * nt);
                    mma16816(acc[mt][nt], ah[mt], bl + 2 * nt);
                    mma16816(acc[mt][nt], al[mt], bh + 2 * nt);
                }
        }
        __syncthreads();
    }

#pragma unroll
    for (int mt = 0; mt < 4; mt++)
#pragma unroll
        for (int nt = 0; nt < 2; nt++)
#pragma unroll
            for (int hf = 0; hf < 2; hf++) {
                int q = q0 + wm * 64 + mt * 16 + (l >> 2) + hf * 8;
                int d = wn * 16 + nt * 8 + (l & 3) * 2;
                float* o = ctx + (size_t)q * EM + h * HD + d;
                o[0] = acc[mt][nt][hf * 2 + 0];
                o[1] = acc[mt][nt][hf * 2 + 1];
            }
}

// ============================================================================
extern "C" void kernel_launch(void* const* d_in, const int* in_sizes, int n_in,
                              void* d_out, int out_size)
{
    const float* hid = (const float*)d_in[0];
    const float* Wq = (const float*)d_in[2];
    const float* bq = (const float*)d_in[3];
    const float* Wk = (const float*)d_in[4];
    const float* bk = (const float*)d_in[5];
    const float* Wv = (const float*)d_in[6];
    const float* bv = (const float*)d_in[7];
    const float* Wo = (const float*)d_in[8];
    const float* bo = (const float*)d_in[9];
    float* out = (float*)d_out;

    float *gq, *gk, *gv, *gctx, *gsc;
    float2* gst;
    cudaGetSymbolAddress((void**)&gq,   g_Q);
    cudaGetSymbolAddress((void**)&gk,   g_K);
    cudaGetSymbolAddress((void**)&gv,   g_V);
    cudaGetSymbolAddress((void**)&gctx, g_ctx);
    cudaGetSymbolAddress((void**)&gsc,  g_scores);
    cudaGetSymbolAddress((void**)&gst,  g_stats);

    __nv_bfloat16 *hH, *hL, *qH, *qL, *kH, *kL, *vH, *vL, *oH, *oL, *cH, *cL;
    __nv_bfloat16 *QsH, *QsL, *KsH, *KsL, *VsH, *VsL;
    cudaGetSymbolAddress((void**)&hH, g_hidH); cudaGetSymbolAddress((void**)&hL, g_hidL);
    cudaGetSymbolAddress((void**)&qH, g_WqH);  cudaGetSymbolAddress((void**)&qL, g_WqL);
    cudaGetSymbolAddress((void**)&kH, g_WkH);  cudaGetSymbolAddress((void**)&kL, g_WkL);
    cudaGetSymbolAddress((void**)&vH, g_WvH);  cudaGetSymbolAddress((void**)&vL, g_WvL);
    cudaGetSymbolAddress((void**)&oH, g_WoH);  cudaGetSymbolAddress((void**)&oL, g_WoL);
    cudaGetSymbolAddress((void**)&cH, g_ctxH); cudaGetSymbolAddress((void**)&cL, g_ctxL);
    cudaGetSymbolAddress((void**)&QsH, g_QsH); cudaGetSymbolAddress((void**)&QsL, g_QsL);
    cudaGetSymbolAddress((void**)&KsH, g_KsH); cudaGetSymbolAddress((void**)&KsL, g_KsL);
    cudaGetSymbolAddress((void**)&VsH, g_VsH); cudaGetSymbolAddress((void**)&VsL, g_VsL);

    cudaFuncSetAttribute(mma_gemm<0, false>, cudaFuncAttributeMaxDynamicSharedMemorySize, SMEM_SZ);
    cudaFuncSetAttribute(mma_gemm<1, true>,  cudaFuncAttributeMaxDynamicSharedMemorySize, SMEM_SZ);
    cudaFuncSetAttribute(scores_mma, cudaFuncAttributeMaxDynamicSharedMemorySize, SC_SMEM);
    cudaFuncSetAttribute(fused_wv,   cudaFuncAttributeMaxDynamicSharedMemorySize, FA_SMEM);

    const size_t n_attn = (size_t)SQ * EM;
    const size_t n_w    = (size_t)NH * SQ * SQ;
    const size_t n_kv   = (size_t)NH * SQ * HD;
    const bool has_w  = (size_t)out_size >= n_attn + n_w;
    const bool has_kv = (size_t)out_size >= n_attn + n_w + 2 * n_kv;
    float* scores = has_w ? (out + n_attn) : gsc;

    const int NCV = SQ * EM;
    split_bf16<<<4096, 256>>>(hid, hH, hL, NCV);
    split_bf16<<<4096, 256>>>(Wq,  qH, qL, NCV);
    split_bf16<<<4096, 256>>>(Wk,  kH, kL, NCV);
    split_bf16<<<4096, 256>>>(Wv,  vH, vL, NCV);
    split_bf16<<<4096, 256>>>(Wo,  oH, oL, NCV);

    dim3 g16(16, 16), blk(256);
    mma_gemm<1, true><<<g16, blk, SMEM_SZ>>>(hH, hL, qH, qL, bq, gq, QsH, QsL, 0.125f);
    mma_gemm<1, true><<<g16, blk, SMEM_SZ>>>(hH, hL, kH, kL, bk, gk, KsH, KsL, 1.0f);
    mma_gemm<1, true><<<g16, blk, SMEM_SZ>>>(hH, hL, vH, vL, bv, gv, VsH, VsL, 1.0f);

    scores_mma<<<dim3(16, 16, NH), blk, SC_SMEM>>>(QsH, QsL, KsH, KsL, scores);
    rowstats_zero<<<dim3(SQ, NH), blk>>>(scores, gst);
    fused_wv<<<dim3(16, NH), blk, FA_SMEM>>>(scores, VsH, VsL, gst, gctx);

    split_bf16<<<4096, 256>>>(gctx, cH, cL, NCV);
    mma_gemm<0, false><<<g16, blk, SMEM_SZ>>>(cH, cL, oH, oL, bo, out, nullptr, nullptr, 1.0f);

    if (has_kv) {
        cudaMemcpyAsync(out + n_attn + n_w, gk, n_kv * sizeof(float),
                        cudaMemcpyDeviceToDevice);
        cudaMemcpyAsync(out + n_attn + n_w + n_kv, gv, n_kv * sizeof(float),
                        cudaMemcpyDeviceToDevice);
    }
}

// round 6
// speedup vs baseline: 1.4499x; 1.4499x over previous
#include <cuda_runtime.h>
#include <cuda_bf16.h>
#include <cstdint>

#define SQ 2048
#define EM 2048
#define NH 32
#define HD 64

// ---------------- device scratch (allocation-free rule) ----------------------
__device__ float g_Q[NH * SQ * HD];
__device__ float g_K[NH * SQ * HD];
__device__ float g_V[NH * SQ * HD];
__device__ float g_ctx[SQ * EM];
__device__ float g_scores[(size_t)NH * SQ * SQ];   // fallback only

__device__ __nv_bfloat16 g_hidH[SQ * EM], g_hidL[SQ * EM];
__device__ __nv_bfloat16 g_WqH[EM * EM],  g_WqL[EM * EM];
__device__ __nv_bfloat16 g_WkH[EM * EM],  g_WkL[EM * EM];
__device__ __nv_bfloat16 g_WvH[EM * EM],  g_WvL[EM * EM];
__device__ __nv_bfloat16 g_WoH[EM * EM],  g_WoL[EM * EM];
__device__ __nv_bfloat16 g_ctxH[SQ * EM], g_ctxL[SQ * EM];
// shaped [h][s][hd] hi/lo splits written by projection epilogues
__device__ __nv_bfloat16 g_QsH[NH * SQ * HD], g_QsL[NH * SQ * HD];
__device__ __nv_bfloat16 g_KsH[NH * SQ * HD], g_KsL[NH * SQ * HD];
__device__ __nv_bfloat16 g_VsH[NH * SQ * HD], g_VsL[NH * SQ * HD];
// bf16 hi/lo of normalized attention weights [h][q][k] (causal tiles only)
__device__ __nv_bfloat16 g_AwH[(size_t)NH * SQ * SQ];
__device__ __nv_bfloat16 g_AwL[(size_t)NH * SQ * SQ];

// ---------------- helpers ----------------------------------------------------
__device__ __forceinline__ uint32_t smem_u32(const void* p) {
    uint32_t a;
    asm("{ .reg .u64 t; cvta.to.shared.u64 t, %1; cvt.u32.u64 %0, t; }"
        : "=r"(a) : "l"(p));
    return a;
}
__device__ __forceinline__ void ldsm4(uint32_t* r, uint32_t addr) {
    asm volatile("ldmatrix.sync.aligned.m8n8.x4.shared.b16 {%0,%1,%2,%3}, [%4];"
                 : "=r"(r[0]), "=r"(r[1]), "=r"(r[2]), "=r"(r[3]) : "r"(addr));
}
__device__ __forceinline__ void ldsm4t(uint32_t* r, uint32_t addr) {
    asm volatile("ldmatrix.sync.aligned.m8n8.x4.trans.shared.b16 {%0,%1,%2,%3}, [%4];"
                 : "=r"(r[0]), "=r"(r[1]), "=r"(r[2]), "=r"(r[3]) : "r"(addr));
}
__device__ __forceinline__ void mma16816(float* c, const uint32_t* a,
                                         const uint32_t* b) {
    asm volatile(
        "mma.sync.aligned.m16n8k16.row.col.f32.bf16.bf16.f32 "
        "{%0,%1,%2,%3}, {%4,%5,%6,%7}, {%8,%9}, {%0,%1,%2,%3};"
        : "+f"(c[0]), "+f"(c[1]), "+f"(c[2]), "+f"(c[3])
        : "r"(a[0]), "r"(a[1]), "r"(a[2]), "r"(a[3]), "r"(b[0]), "r"(b[1]));
}
__device__ __forceinline__ uint32_t sw(uint32_t off) {
    return off ^ ((off >> 3) & 0x70);
}

// fp32 -> bf16 hi/lo split
__global__ void __launch_bounds__(256)
split_bf16(const float* __restrict__ x, __nv_bfloat16* __restrict__ hi,
           __nv_bfloat16* __restrict__ lo, int n)
{
    int i = (blockIdx.x * 256 + threadIdx.x) * 4;
    if (i >= n) return;
    float4 v = *(const float4*)(x + i);
    __nv_bfloat16 h[4], l[4];
    float vv[4] = {v.x, v.y, v.z, v.w};
#pragma unroll
    for (int j = 0; j < 4; j++) {
        h[j] = __float2bfloat16(vv[j]);
        l[j] = __float2bfloat16(vv[j] - __bfloat162float(h[j]));
    }
    *(uint2*)(hi + i) = *(const uint2*)h;
    *(uint2*)(lo + i) = *(const uint2*)l;
}

// ============================================================================
// Shared MMA stage over 4 operand tiles (Ah,Al,Bh,Bl), 128 rows x 128B each.
// ============================================================================
#define TILE_B 16384

__device__ __forceinline__ void
mma_stage(uint32_t base, int wm, int wn, int l, float acc[4][4][4])
{
    const uint32_t aH = base, aL = base + TILE_B;
    const uint32_t bH = base + 2 * TILE_B, bL = base + 3 * TILE_B;
#pragma unroll
    for (int ks = 0; ks < 4; ks++) {
        uint32_t ah[4][4], al[4][4], bh[4][2], bl[4][2];
#pragma unroll
        for (int mt = 0; mt < 4; mt++) {
            int row = wm * 64 + mt * 16 + (l & 15);
            int chk = ks * 2 + (l >> 4);
            uint32_t off = sw(row * 128 + chk * 16);
            ldsm4(ah[mt], aH + off);
            ldsm4(al[mt], aL + off);
        }
#pragma unroll
        for (int j = 0; j < 2; j++) {
            int row = wn * 32 + j * 16 + (l & 7) + ((l >> 4) << 3);
            int chk = ks * 2 + ((l >> 3) & 1);
            uint32_t off = sw(row * 128 + chk * 16);
            uint32_t t4[4];
            ldsm4(t4, bH + off);
            bh[2 * j][0] = t4[0]; bh[2 * j][1] = t4[1];
            bh[2 * j + 1][0] = t4[2]; bh[2 * j + 1][1] = t4[3];
            ldsm4(t4, bL + off);
            bl[2 * j][0] = t4[0]; bl[2 * j][1] = t4[1];
            bl[2 * j + 1][0] = t4[2]; bl[2 * j + 1][1] = t4[3];
        }
#pragma unroll
        for (int mt = 0; mt < 4; mt++)
#pragma unroll
            for (int nt = 0; nt < 4; nt++) {
                mma16816(acc[mt][nt], ah[mt], bh[nt]);
                mma16816(acc[mt][nt], ah[mt], bl[nt]);
                mma16816(acc[mt][nt], al[mt], bh[nt]);
            }
    }
}

// ============================================================================
// Tensor-core split-bf16 GEMM: C = (A @ B^T + bias) * scale, 2048^3.
// ============================================================================
#define SMEM_SZ (8 * TILE_B)

template <int MODE, bool SPLIT>
__global__ void __launch_bounds__(256)
mma_gemm(const __nv_bfloat16* __restrict__ Ah, const __nv_bfloat16* __restrict__ Al,
         const __nv_bfloat16* __restrict__ Bh, const __nv_bfloat16* __restrict__ Bl,
         const float* __restrict__ bias, float* __restrict__ C,
         __nv_bfloat16* __restrict__ Chi, __nv_bfloat16* __restrict__ Clo,
         float scale)
{
    extern __shared__ char smem[];
    const uint32_t sb = smem_u32(smem);
    const int tid = threadIdx.x;
    const int w = tid >> 5, l = tid & 31;
    const int wm = w >> 2, wn = w & 3;
    const int m0 = blockIdx.y * 128;
    const int n0 = blockIdx.x * 128;

    auto issue = [&](int s, int k0) {
#pragma unroll
        for (int it = 0; it < 16; it++) {
            int c = tid + it * 256;
            int o = c >> 10;
            int row = (c >> 3) & 127;
            int chk = c & 7;
            const __nv_bfloat16* p = (o == 0) ? Ah : (o == 1) ? Al
                                   : (o == 2) ? Bh : Bl;
            int rb = (o < 2) ? m0 : n0;
            const void* g = p + (size_t)(rb + row) * 2048 + k0 + chk * 8;
            uint32_t d = sb + (uint32_t)(s * 4 + o) * TILE_B
                         + sw(row * 128 + chk * 16);
            asm volatile("cp.async.cg.shared.global [%0], [%1], 16;\n"
                         :: "r"(d), "l"(g));
        }
        asm volatile("cp.async.commit_group;\n" ::: "memory");
    };

    float acc[4][4][4] = {};
    issue(0, 0);

    const int NS = 2048 / 64;
    for (int i = 0; i < NS; i++) {
        if (i + 1 < NS) {
            issue((i + 1) & 1, (i + 1) * 64);
            asm volatile("cp.async.wait_group 1;\n" ::: "memory");
        } else {
            asm volatile("cp.async.wait_group 0;\n" ::: "memory");
        }
        __syncthreads();
        mma_stage(sb + (uint32_t)((i & 1) * 4) * TILE_B, wm, wn, l, acc);
        __syncthreads();
    }

#pragma unroll
    for (int mt = 0; mt < 4; mt++) {
#pragma unroll
        for (int nt = 0; nt < 4; nt++) {
            int m = m0 + wm * 64 + mt * 16 + (l >> 2);
            int n = n0 + wn * 32 + nt * 8 + (l & 3) * 2;
#pragma unroll
            for (int hf = 0; hf < 2; hf++) {
                int row = m + hf * 8;
                float v0 = (acc[mt][nt][hf * 2 + 0] + bias[n]) * scale;
                float v1 = (acc[mt][nt][hf * 2 + 1] + bias[n + 1]) * scale;
                size_t idx;
                if (MODE == 0)
                    idx = (size_t)row * 2048 + n;
                else
                    idx = (((size_t)(n >> 6)) * SQ + row) * HD + (n & 63);
                C[idx] = v0;
                C[idx + 1] = v1;
                if (SPLIT) {
                    __nv_bfloat16 h0 = __float2bfloat16(v0);
                    __nv_bfloat16 h1 = __float2bfloat16(v1);
                    __nv_bfloat16 l0 = __float2bfloat16(v0 - __bfloat162float(h0));
                    __nv_bfloat16 l1 = __float2bfloat16(v1 - __bfloat162float(h1));
                    Chi[idx] = h0; Chi[idx + 1] = h1;
                    Clo[idx] = l0; Clo[idx + 1] = l1;
                }
            }
        }
    }
}

// ============================================================================
// Tensor-core scores: scores[h] = Qs @ Ks^T per head, K=64 (one stage).
// ============================================================================
#define SC_SMEM (4 * TILE_B)

__global__ void __launch_bounds__(256)
scores_mma(const __nv_bfloat16* __restrict__ Qh, const __nv_bfloat16* __restrict__ Ql,
           const __nv_bfloat16* __restrict__ Kh, const __nv_bfloat16* __restrict__ Kl,
           float* __restrict__ scores)
{
    if (blockIdx.x > blockIdx.y) return;
    extern __shared__ char smem[];
    const uint32_t sb = smem_u32(smem);
    const int tid = threadIdx.x;
    const int w = tid >> 5, l = tid & 31;
    const int wm = w >> 2, wn = w & 3;
    const int h  = blockIdx.z;
    const int q0 = blockIdx.y * 128;
    const int k0 = blockIdx.x * 128;
    const size_t hb = (size_t)h * SQ * HD;

#pragma unroll
    for (int it = 0; it < 16; it++) {
        int c = tid + it * 256;
        int o = c >> 10;
        int row = (c >> 3) & 127;
        int chk = c & 7;
        const __nv_bfloat16* p = (o == 0) ? Qh : (o == 1) ? Ql
                               : (o == 2) ? Kh : Kl;
        int rb = (o < 2) ? q0 : k0;
        const void* g = p + hb + (size_t)(rb + row) * HD + chk * 8;
        uint32_t d = sb + (uint32_t)o * TILE_B + sw(row * 128 + chk * 16);
        asm volatile("cp.async.cg.shared.global [%0], [%1], 16;\n"
                     :: "r"(d), "l"(g));
    }
    asm volatile("cp.async.commit_group;\n" ::: "memory");
    asm volatile("cp.async.wait_group 0;\n" ::: "memory");
    __syncthreads();

    float acc[4][4][4] = {};
    mma_stage(sb, wm, wn, l, acc);

    float* Co = scores + (size_t)h * SQ * SQ;
#pragma unroll
    for (int mt = 0; mt < 4; mt++)
#pragma unroll
        for (int nt = 0; nt < 4; nt++) {
            int m = q0 + wm * 64 + mt * 16 + (l >> 2);
            int n = k0 + wn * 32 + nt * 8 + (l & 3) * 2;
#pragma unroll
            for (int hf = 0; hf < 2; hf++) {
                size_t idx = (size_t)(m + hf * 8) * SQ + n;
                Co[idx]     = acc[mt][nt][hf * 2 + 0];
                Co[idx + 1] = acc[mt][nt][hf * 2 + 1];
            }
        }
}

// ============================================================================
// Causal softmax in place + bf16 hi/lo side write (causal 128-tiles only).
// ============================================================================
__global__ void __launch_bounds__(256)
softmax_causal(float* __restrict__ scores,
               __nv_bfloat16* __restrict__ AwH, __nv_bfloat16* __restrict__ AwL)
{
    const int q = blockIdx.x;
    const int h = blockIdx.y;
    const int t = threadIdx.x;
    const size_t rbase = ((size_t)h * SQ + q) * SQ;
    float* row = scores + rbase;

    const float NEG_INF = __int_as_float(0xff800000);
    float v[8];
    float mx = NEG_INF;
#pragma unroll
    for (int i = 0; i < 8; i++) {
        int idx = t + i * 256;
        v[i] = (idx <= q) ? row[idx] : NEG_INF;
        mx = fmaxf(mx, v[i]);
    }
    __shared__ float red[256];
    red[t] = mx; __syncthreads();
    for (int s2 = 128; s2 > 0; s2 >>= 1) {
        if (t < s2) red[t] = fmaxf(red[t], red[t + s2]);
        __syncthreads();
    }
    mx = red[0]; __syncthreads();

    float sum = 0.0f;
#pragma unroll
    for (int i = 0; i < 8; i++) {
        v[i] = __expf(v[i] - mx);
        sum += v[i];
    }
    red[t] = sum; __syncthreads();
    for (int s2 = 128; s2 > 0; s2 >>= 1) {
        if (t < s2) red[t] += red[t + s2];
        __syncthreads();
    }
    float inv = 1.0f / red[0];

    const int kend = ((q >> 7) + 1) << 7;   // end of diagonal 128-tile
#pragma unroll
    for (int i = 0; i < 8; i++) {
        int idx = t + i * 256;
        float wv = v[i] * inv;
        row[idx] = wv;
        if (idx < kend) {
            __nv_bfloat16 hh = __float2bfloat16(wv);
            __nv_bfloat16 ll = __float2bfloat16(wv - __bfloat162float(hh));
            AwH[rbase + idx] = hh;
            AwL[rbase + idx] = ll;
        }
    }
}

// ============================================================================
// Tensor-core attn_v: ctx[q][h*64+d] = W[h] @ V[h] with split-bf16 operands.
// Per CTA: (q-tile 128, head). cp.async double-buffered k-tiles of 128.
// Buffer layout (per buf, 96KB): WH[2][128][64], WL[2][128][64], VH, VL.
// ============================================================================
#define AV_WH 0
#define AV_WL 32768
#define AV_VH 65536
#define AV_VL 81920
#define AV_BUF 98304
#define AV_SMEM (2 * AV_BUF)   // 196608

__global__ void __launch_bounds__(256)
attn_v_mma(const __nv_bfloat16* __restrict__ AwH, const __nv_bfloat16* __restrict__ AwL,
           const __nv_bfloat16* __restrict__ VsH, const __nv_bfloat16* __restrict__ VsL,
           float* __restrict__ ctx)
{
    extern __shared__ char smem[];
    const uint32_t sb = smem_u32(smem);
    const int tid = threadIdx.x;
    const int w = tid >> 5, l = tid & 31;
    const int wm = w >> 2, wn = w & 3;           // wm 0..1 (64 rows), wn 0..3 (16 cols)
    const int h  = blockIdx.y;
    const int qt = 15 - blockIdx.x;              // big tiles first
    const int q0 = qt * 128;
    const size_t wb = ((size_t)h * SQ + q0) * SQ;
    const size_t vb = (size_t)h * SQ * HD;

    auto issue = [&](int s, int k0) {
        const uint32_t bufb = sb + (uint32_t)s * AV_BUF;
        // W hi/lo: 2 ops x 2048 chunks of 16B
#pragma unroll
        for (int it = 0; it < 16; it++) {
            int c = tid + it * 256;
            int op = c >> 11;                    // 0 = WH, 1 = WL
            int cc = c & 2047;
            int row = cc >> 4;                   // q row 0..127
            int ch  = cc & 15;                   // 16B chunk along k
            const __nv_bfloat16* p = op ? AwL : AwH;
            const void* g = p + wb + (size_t)row * SQ + k0 + ch * 8;
            uint32_t d = bufb + (op ? AV_WL : AV_WH) + (uint32_t)(ch >> 3) * 16384
                         + sw(row * 128 + (ch & 7) * 16);
            asm volatile("cp.async.cg.shared.global [%0], [%1], 16;\n"
                         :: "r"(d), "l"(g));
        }
        // V hi/lo: 2 ops x 1024 chunks
#pragma unroll
        for (int it = 0; it < 8; it++) {
            int c = tid + it * 256;
            int op = c >> 10;
            int cc = c & 1023;
            int row = cc >> 3;
            int ch  = cc & 7;
            const __nv_bfloat16* p = op ? VsL : VsH;
            const void* g = p + vb + (size_t)(k0 + row) * HD + ch * 8;
            uint32_t d = bufb + (op ? AV_VL : AV_VH) + sw(row * 128 + ch * 16);
            asm volatile("cp.async.cg.shared.global [%0], [%1], 16;\n"
                         :: "r"(d), "l"(g));
        }
        asm volatile("cp.async.commit_group;\n" ::: "memory");
    };

    float acc[4][2][4] = {};
    const int NT = qt + 1;
    issue(0, 0);

    for (int i = 0; i < NT; i++) {
        if (i + 1 < NT) {
            issue((i + 1) & 1, (i + 1) * 128);
            asm volatile("cp.async.wait_group 1;\n" ::: "memory");
        } else {
            asm volatile("cp.async.wait_group 0;\n" ::: "memory");
        }
        __syncthreads();

        const uint32_t bufb = sb + (uint32_t)(i & 1) * AV_BUF;
#pragma unroll
        for (int ks = 0; ks < 8; ks++) {
            int half = ks >> 2, ksl = ks & 3;
            uint32_t ah[4][4], al[4][4];
#pragma unroll
            for (int mt = 0; mt < 4; mt++) {
                int rowq = wm * 64 + mt * 16 + (l & 15);
                int chk = ksl * 2 + (l >> 4);
                uint32_t off = sw(rowq * 128 + chk * 16);
                ldsm4(ah[mt], bufb + AV_WH + half * 16384 + off);
                ldsm4(al[mt], bufb + AV_WL + half * 16384 + off);
            }
            uint32_t bh[4], bl[4];
            {
                int rowk = ks * 16 + (l & 15);
                int colb = wn * 32 + (l >> 4) * 16;
                uint32_t off = sw(rowk * 128 + colb);
                ldsm4t(bh, bufb + AV_VH + off);
                ldsm4t(bl, bufb + AV_VL + off);
            }
#pragma unroll
            for (int mt = 0; mt < 4; mt++)
#pragma unroll
                for (int nt = 0; nt < 2; nt++) {
                    mma16816(acc[mt][nt], ah[mt], bh + 2 * nt);
                    mma16816(acc[mt][nt], ah[mt], bl + 2 * nt);
                    mma16816(acc[mt][nt], al[mt], bh + 2 * nt);
                }
        }
        __syncthreads();
    }

#pragma unroll
    for (int mt = 0; mt < 4; mt++)
#pragma unroll
        for (int nt = 0; nt < 2; nt++)
#pragma unroll
            for (int hf = 0; hf < 2; hf++) {
                int q = q0 + wm * 64 + mt * 16 + (l >> 2) + hf * 8;
                int d = wn * 16 + nt * 8 + (l & 3) * 2;
                float* o = ctx + (size_t)q * EM + h * HD + d;
                o[0] = acc[mt][nt][hf * 2 + 0];
                o[1] = acc[mt][nt][hf * 2 + 1];
            }
}

// ============================================================================
extern "C" void kernel_launch(void* const* d_in, const int* in_sizes, int n_in,
                              void* d_out, int out_size)
{
    const float* hid = (const float*)d_in[0];
    const float* Wq = (const float*)d_in[2];
    const float* bq = (const float*)d_in[3];
    const float* Wk = (const float*)d_in[4];
    const float* bk = (const float*)d_in[5];
    const float* Wv = (const float*)d_in[6];
    const float* bv = (const float*)d_in[7];
    const float* Wo = (const float*)d_in[8];
    const float* bo = (const float*)d_in[9];
    float* out = (float*)d_out;

    float *gq, *gk, *gv, *gctx, *gsc;
    cudaGetSymbolAddress((void**)&gq,   g_Q);
    cudaGetSymbolAddress((void**)&gk,   g_K);
    cudaGetSymbolAddress((void**)&gv,   g_V);
    cudaGetSymbolAddress((void**)&gctx, g_ctx);
    cudaGetSymbolAddress((void**)&gsc,  g_scores);

    __nv_bfloat16 *hH, *hL, *qH, *qL, *kH, *kL, *vH, *vL, *oH, *oL, *cH, *cL;
    __nv_bfloat16 *QsH, *QsL, *KsH, *KsL, *VsH, *VsL, *AwH, *AwL;
    cudaGetSymbolAddress((void**)&hH, g_hidH); cudaGetSymbolAddress((void**)&hL, g_hidL);
    cudaGetSymbolAddress((void**)&qH, g_WqH);  cudaGetSymbolAddress((void**)&qL, g_WqL);
    cudaGetSymbolAddress((void**)&kH, g_WkH);  cudaGetSymbolAddress((void**)&kL, g_WkL);
    cudaGetSymbolAddress((void**)&vH, g_WvH);  cudaGetSymbolAddress((void**)&vL, g_WvL);
    cudaGetSymbolAddress((void**)&oH, g_WoH);  cudaGetSymbolAddress((void**)&oL, g_WoL);
    cudaGetSymbolAddress((void**)&cH, g_ctxH); cudaGetSymbolAddress((void**)&cL, g_ctxL);
    cudaGetSymbolAddress((void**)&QsH, g_QsH); cudaGetSymbolAddress((void**)&QsL, g_QsL);
    cudaGetSymbolAddress((void**)&KsH, g_KsH); cudaGetSymbolAddress((void**)&KsL, g_KsL);
    cudaGetSymbolAddress((void**)&VsH, g_VsH); cudaGetSymbolAddress((void**)&VsL, g_VsL);
    cudaGetSymbolAddress((void**)&AwH, g_AwH); cudaGetSymbolAddress((void**)&AwL, g_AwL);

    cudaFuncSetAttribute(mma_gemm<0, false>, cudaFuncAttributeMaxDynamicSharedMemorySize, SMEM_SZ);
    cudaFuncSetAttribute(mma_gemm<1, true>,  cudaFuncAttributeMaxDynamicSharedMemorySize, SMEM_SZ);
    cudaFuncSetAttribute(scores_mma, cudaFuncAttributeMaxDynamicSharedMemorySize, SC_SMEM);
    cudaFuncSetAttribute(attn_v_mma, cudaFuncAttributeMaxDynamicSharedMemorySize, AV_SMEM);

    const size_t n_attn = (size_t)SQ * EM;
    const size_t n_w    = (size_t)NH * SQ * SQ;
    const size_t n_kv   = (size_t)NH * SQ * HD;
    const bool has_w  = (size_t)out_size >= n_attn + n_w;
    const bool has_kv = (size_t)out_size >= n_attn + n_w + 2 * n_kv;
    float* scores = has_w ? (out + n_attn) : gsc;

    const int NCV = SQ * EM;
    split_bf16<<<4096, 256>>>(hid, hH, hL, NCV);
    split_bf16<<<4096, 256>>>(Wq,  qH, qL, NCV);
    split_bf16<<<4096, 256>>>(Wk,  kH, kL, NCV);
    split_bf16<<<4096, 256>>>(Wv,  vH, vL, NCV);
    split_bf16<<<4096, 256>>>(Wo,  oH, oL, NCV);

    dim3 g16(16, 16), blk(256);
    mma_gemm<1, true><<<g16, blk, SMEM_SZ>>>(hH, hL, qH, qL, bq, gq, QsH, QsL, 0.125f);
    mma_gemm<1, true><<<g16, blk, SMEM_SZ>>>(hH, hL, kH, kL, bk, gk, KsH, KsL, 1.0f);
    mma_gemm<1, true><<<g16, blk, SMEM_SZ>>>(hH, hL, vH, vL, bv, gv, VsH, VsL, 1.0f);

    scores_mma<<<dim3(16, 16, NH), blk, SC_SMEM>>>(QsH, QsL, KsH, KsL, scores);
    softmax_causal<<<dim3(SQ, NH), blk>>>(scores, AwH, AwL);
    attn_v_mma<<<dim3(16, NH), blk, AV_SMEM>>>(AwH, AwL, VsH, VsL, gctx);

    split_bf16<<<4096, 256>>>(gctx, cH, cL, NCV);
    mma_gemm<0, false><<<g16, blk, SMEM_SZ>>>(cH, cL, oH, oL, bo, out, nullptr, nullptr, 1.0f);

    if (has_kv) {
        cudaMemcpyAsync(out + n_attn + n_w, gk, n_kv * sizeof(float),
                        cudaMemcpyDeviceToDevice);
        cudaMemcpyAsync(out + n_attn + n_w + n_kv, gv, n_kv * sizeof(float),
                        cudaMemcpyDeviceToDevice);
    }
}

// round 7
// speedup vs baseline: 1.5738x; 1.0854x over previous
#include <cuda_runtime.h>
#include <cuda_fp16.h>
#include <cstdint>

#define SQ 2048
#define EM 2048
#define NH 32
#define HD 64

// ---------------- device scratch (allocation-free rule) ----------------------
__device__ float g_Q[NH * SQ * HD];
__device__ float g_K[NH * SQ * HD];
__device__ float g_V[NH * SQ * HD];
__device__ float g_scores[(size_t)NH * SQ * SQ];   // fallback only

__device__ __half g_hidH[SQ * EM], g_hidL[SQ * EM];
__device__ __half g_WqH[EM * EM],  g_WqL[EM * EM];
__device__ __half g_WkH[EM * EM],  g_WkL[EM * EM];
__device__ __half g_WvH[EM * EM],  g_WvL[EM * EM];
__device__ __half g_WoH[EM * EM],  g_WoL[EM * EM];
__device__ __half g_ctxH[SQ * EM], g_ctxL[SQ * EM];
// shaped [h][s][hd] hi/lo splits written by projection epilogues
__device__ __half g_QsH[NH * SQ * HD], g_QsL[NH * SQ * HD];
__device__ __half g_KsH[NH * SQ * HD], g_KsL[NH * SQ * HD];
__device__ __half g_VsH[NH * SQ * HD], g_VsL[NH * SQ * HD];
// fp16 hi/lo of normalized attention weights (causal 128-tiles only)
__device__ __half g_AwH[(size_t)NH * SQ * SQ];
__device__ __half g_AwL[(size_t)NH * SQ * SQ];

// ---------------- helpers ----------------------------------------------------
__device__ __forceinline__ uint32_t smem_u32(const void* p) {
    uint32_t a;
    asm("{ .reg .u64 t; cvta.to.shared.u64 t, %1; cvt.u32.u64 %0, t; }"
        : "=r"(a) : "l"(p));
    return a;
}
__device__ __forceinline__ void ldsm4(uint32_t* r, uint32_t addr) {
    asm volatile("ldmatrix.sync.aligned.m8n8.x4.shared.b16 {%0,%1,%2,%3}, [%4];"
                 : "=r"(r[0]), "=r"(r[1]), "=r"(r[2]), "=r"(r[3]) : "r"(addr));
}
__device__ __forceinline__ void ldsm4t(uint32_t* r, uint32_t addr) {
    asm volatile("ldmatrix.sync.aligned.m8n8.x4.trans.shared.b16 {%0,%1,%2,%3}, [%4];"
                 : "=r"(r[0]), "=r"(r[1]), "=r"(r[2]), "=r"(r[3]) : "r"(addr));
}
__device__ __forceinline__ void mma16816(float* c, const uint32_t* a,
                                         const uint32_t* b) {
    asm volatile(
        "mma.sync.aligned.m16n8k16.row.col.f32.f16.f16.f32 "
        "{%0,%1,%2,%3}, {%4,%5,%6,%7}, {%8,%9}, {%0,%1,%2,%3};"
        : "+f"(c[0]), "+f"(c[1]), "+f"(c[2]), "+f"(c[3])
        : "r"(a[0]), "r"(a[1]), "r"(a[2]), "r"(a[3]), "r"(b[0]), "r"(b[1]));
}
__device__ __forceinline__ uint32_t sw(uint32_t off) {
    return off ^ ((off >> 3) & 0x70);
}

// fp32 -> fp16 hi/lo split, grid-stride (2 iters at n=4M, grid 2048)
__global__ void __launch_bounds__(256)
split_f16(const float* __restrict__ x, __half* __restrict__ hi,
          __half* __restrict__ lo, int n)
{
    const int stride = gridDim.x * 256 * 4;
    for (int i = (blockIdx.x * 256 + threadIdx.x) * 4; i < n; i += stride) {
        float4 v = *(const float4*)(x + i);
        __half h[4], l[4];
        float vv[4] = {v.x, v.y, v.z, v.w};
#pragma unroll
        for (int j = 0; j < 4; j++) {
            h[j] = __float2half_rn(vv[j]);
            l[j] = __float2half_rn(vv[j] - __half2float(h[j]));
        }
        *(uint2*)(hi + i) = *(const uint2*)h;
        *(uint2*)(lo + i) = *(const uint2*)l;
    }
}

// ============================================================================
// MMA stage over operand tiles (Ah,Al,Bh[,Bl]), 128 rows x 128B each.
// NPROD==3: AhBh + AhBl + AlBh.  NPROD==2: AhBh + AlBh (Bl never touched).
// ============================================================================
#define TILE_B 16384

template <int NPROD>
__device__ __forceinline__ void
mma_stage(uint32_t base, int wm, int wn, int l, float acc[4][4][4])
{
    const uint32_t aH = base, aL = base + TILE_B;
    const uint32_t bH = base + 2 * TILE_B, bL = base + 3 * TILE_B;
#pragma unroll
    for (int ks = 0; ks < 4; ks++) {
        uint32_t ah[4][4], al[4][4], bh[4][2], bl[4][2];
#pragma unroll
        for (int mt = 0; mt < 4; mt++) {
            int row = wm * 64 + mt * 16 + (l & 15);
            int chk = ks * 2 + (l >> 4);
            uint32_t off = sw(row * 128 + chk * 16);
            ldsm4(ah[mt], aH + off);
            ldsm4(al[mt], aL + off);
        }
#pragma unroll
        for (int j = 0; j < 2; j++) {
            int row = wn * 32 + j * 16 + (l & 7) + ((l >> 4) << 3);
            int chk = ks * 2 + ((l >> 3) & 1);
            uint32_t off = sw(row * 128 + chk * 16);
            uint32_t t4[4];
            ldsm4(t4, bH + off);
            bh[2 * j][0] = t4[0]; bh[2 * j][1] = t4[1];
            bh[2 * j + 1][0] = t4[2]; bh[2 * j + 1][1] = t4[3];
            if (NPROD == 3) {
                ldsm4(t4, bL + off);
                bl[2 * j][0] = t4[0]; bl[2 * j][1] = t4[1];
                bl[2 * j + 1][0] = t4[2]; bl[2 * j + 1][1] = t4[3];
            }
        }
#pragma unroll
        for (int mt = 0; mt < 4; mt++)
#pragma unroll
            for (int nt = 0; nt < 4; nt++) {
                mma16816(acc[mt][nt], ah[mt], bh[nt]);
                if (NPROD == 3) mma16816(acc[mt][nt], ah[mt], bl[nt]);
                mma16816(acc[mt][nt], al[mt], bh[nt]);
            }
    }
}

// ============================================================================
// Tensor-core split-fp16 GEMM: C = (A @ B^T + bias) * scale, 2048^3.
// ============================================================================
#define SMEM_SZ (8 * TILE_B)

template <int MODE, bool SPLIT, int NPROD>
__global__ void __launch_bounds__(256)
mma_gemm(const __half* __restrict__ Ah, const __half* __restrict__ Al,
         const __half* __restrict__ Bh, const __half* __restrict__ Bl,
         const float* __restrict__ bias, float* __restrict__ C,
         __half* __restrict__ Chi, __half* __restrict__ Clo, float scale)
{
    extern __shared__ char smem[];
    const uint32_t sb = smem_u32(smem);
    const int tid = threadIdx.x;
    const int w = tid >> 5, l = tid & 31;
    const int wm = w >> 2, wn = w & 3;
    const int m0 = blockIdx.y * 128;
    const int n0 = blockIdx.x * 128;

    auto issue = [&](int s, int k0) {
#pragma unroll
        for (int it = 0; it < 16; it++) {
            if (NPROD == 2 && it >= 12) continue;   // skip Bl tile
            int c = tid + it * 256;
            int o = c >> 10;
            int row = (c >> 3) & 127;
            int chk = c & 7;
            const __half* p = (o == 0) ? Ah : (o == 1) ? Al
                             : (o == 2) ? Bh : Bl;
            int rb = (o < 2) ? m0 : n0;
            const void* g = p + (size_t)(rb + row) * 2048 + k0 + chk * 8;
            uint32_t d = sb + (uint32_t)(s * 4 + o) * TILE_B
                         + sw(row * 128 + chk * 16);
            asm volatile("cp.async.cg.shared.global [%0], [%1], 16;\n"
                         :: "r"(d), "l"(g));
        }
        asm volatile("cp.async.commit_group;\n" ::: "memory");
    };

    float acc[4][4][4] = {};
    issue(0, 0);

    const int NS = 2048 / 64;
    for (int i = 0; i < NS; i++) {
        if (i + 1 < NS) {
            issue((i + 1) & 1, (i + 1) * 64);
            asm volatile("cp.async.wait_group 1;\n" ::: "memory");
        } else {
            asm volatile("cp.async.wait_group 0;\n" ::: "memory");
        }
        __syncthreads();
        mma_stage<NPROD>(sb + (uint32_t)((i & 1) * 4) * TILE_B, wm, wn, l, acc);
        __syncthreads();
    }

#pragma unroll
    for (int mt = 0; mt < 4; mt++) {
#pragma unroll
        for (int nt = 0; nt < 4; nt++) {
            int m = m0 + wm * 64 + mt * 16 + (l >> 2);
            int n = n0 + wn * 32 + nt * 8 + (l & 3) * 2;
#pragma unroll
            for (int hf = 0; hf < 2; hf++) {
                int row = m + hf * 8;
                float v0 = (acc[mt][nt][hf * 2 + 0] + bias[n]) * scale;
                float v1 = (acc[mt][nt][hf * 2 + 1] + bias[n + 1]) * scale;
                size_t idx;
                if (MODE == 0)
                    idx = (size_t)row * 2048 + n;
                else
                    idx = (((size_t)(n >> 6)) * SQ + row) * HD + (n & 63);
                C[idx] = v0;
                C[idx + 1] = v1;
                if (SPLIT) {
                    __half h0 = __float2half_rn(v0);
                    __half h1 = __float2half_rn(v1);
                    __half l0 = __float2half_rn(v0 - __half2float(h0));
                    __half l1 = __float2half_rn(v1 - __half2float(h1));
                    Chi[idx] = h0; Chi[idx + 1] = h1;
                    Clo[idx] = l0; Clo[idx + 1] = l1;
                }
            }
        }
    }
}

// ============================================================================
// Tensor-core scores: scores[h] = Qs @ Ks^T per head, K=64 (one stage).
// ============================================================================
#define SC_SMEM (4 * TILE_B)

__global__ void __launch_bounds__(256)
scores_mma(const __half* __restrict__ Qh, const __half* __restrict__ Ql,
           const __half* __restrict__ Kh, const __half* __restrict__ Kl,
           float* __restrict__ scores)
{
    if (blockIdx.x > blockIdx.y) return;
    extern __shared__ char smem[];
    const uint32_t sb = smem_u32(smem);
    const int tid = threadIdx.x;
    const int w = tid >> 5, l = tid & 31;
    const int wm = w >> 2, wn = w & 3;
    const int h  = blockIdx.z;
    const int q0 = blockIdx.y * 128;
    const int k0 = blockIdx.x * 128;
    const size_t hb = (size_t)h * SQ * HD;

#pragma unroll
    for (int it = 0; it < 16; it++) {
        int c = tid + it * 256;
        int o = c >> 10;
        int row = (c >> 3) & 127;
        int chk = c & 7;
        const __half* p = (o == 0) ? Qh : (o == 1) ? Ql
                         : (o == 2) ? Kh : Kl;
        int rb = (o < 2) ? q0 : k0;
        const void* g = p + hb + (size_t)(rb + row) * HD + chk * 8;
        uint32_t d = sb + (uint32_t)o * TILE_B + sw(row * 128 + chk * 16);
        asm volatile("cp.async.cg.shared.global [%0], [%1], 16;\n"
                     :: "r"(d), "l"(g));
    }
    asm volatile("cp.async.commit_group;\n" ::: "memory");
    asm volatile("cp.async.wait_group 0;\n" ::: "memory");
    __syncthreads();

    float acc[4][4][4] = {};
    mma_stage<3>(sb, wm, wn, l, acc);

    float* Co = scores + (size_t)h * SQ * SQ;
#pragma unroll
    for (int mt = 0; mt < 4; mt++)
#pragma unroll
        for (int nt = 0; nt < 4; nt++) {
            int m = q0 + wm * 64 + mt * 16 + (l >> 2);
            int n = k0 + wn * 32 + nt * 8 + (l & 3) * 2;
#pragma unroll
            for (int hf = 0; hf < 2; hf++) {
                size_t idx = (size_t)(m + hf * 8) * SQ + n;
                Co[idx]     = acc[mt][nt][hf * 2 + 0];
                Co[idx + 1] = acc[mt][nt][hf * 2 + 1];
            }
        }
}

// ============================================================================
// Causal softmax in place + fp16 hi/lo side write (causal 128-tiles only).
// ============================================================================
__global__ void __launch_bounds__(256)
softmax_causal(float* __restrict__ scores,
               __half* __restrict__ AwH, __half* __restrict__ AwL)
{
    const int q = blockIdx.x;
    const int h = blockIdx.y;
    const int t = threadIdx.x;
    const size_t rbase = ((size_t)h * SQ + q) * SQ;
    float* row = scores + rbase;

    const float NEG_INF = __int_as_float(0xff800000);
    float v[8];
    float mx = NEG_INF;
#pragma unroll
    for (int i = 0; i < 8; i++) {
        int idx = t + i * 256;
        v[i] = (idx <= q) ? row[idx] : NEG_INF;
        mx = fmaxf(mx, v[i]);
    }
    __shared__ float red[256];
    red[t] = mx; __syncthreads();
    for (int s2 = 128; s2 > 0; s2 >>= 1) {
        if (t < s2) red[t] = fmaxf(red[t], red[t + s2]);
        __syncthreads();
    }
    mx = red[0]; __syncthreads();

    float sum = 0.0f;
#pragma unroll
    for (int i = 0; i < 8; i++) {
        v[i] = __expf(v[i] - mx);
        sum += v[i];
    }
    red[t] = sum; __syncthreads();
    for (int s2 = 128; s2 > 0; s2 >>= 1) {
        if (t < s2) red[t] += red[t + s2];
        __syncthreads();
    }
    float inv = 1.0f / red[0];

    const int kend = ((q >> 7) + 1) << 7;   // end of diagonal 128-tile
#pragma unroll
    for (int i = 0; i < 8; i++) {
        int idx = t + i * 256;
        float wv = v[i] * inv;
        row[idx] = wv;
        if (idx < kend) {
            __half hh = __float2half_rn(wv);
            __half ll = __float2half_rn(wv - __half2float(hh));
            AwH[rbase + idx] = hh;
            AwL[rbase + idx] = ll;
        }
    }
}

// ============================================================================
// Tensor-core attn_v: ctx = W @ V (split fp16, 3-product). Epilogue writes
// ctx directly as fp16 hi/lo in [s][e] layout (feeds 2-product out-proj).
// ============================================================================
#define AV_WH 0
#define AV_WL 32768
#define AV_VH 65536
#define AV_VL 81920
#define AV_BUF 98304
#define AV_SMEM (2 * AV_BUF)

__global__ void __launch_bounds__(256)
attn_v_mma(const __half* __restrict__ AwH, const __half* __restrict__ AwL,
           const __half* __restrict__ VsH, const __half* __restrict__ VsL,
           __half* __restrict__ ctxH, __half* __restrict__ ctxL)
{
    extern __shared__ char smem[];
    const uint32_t sb = smem_u32(smem);
    const int tid = threadIdx.x;
    const int w = tid >> 5, l = tid & 31;
    const int wm = w >> 2, wn = w & 3;
    const int h  = blockIdx.y;
    const int qt = 15 - blockIdx.x;
    const int q0 = qt * 128;
    const size_t wb = ((size_t)h * SQ + q0) * SQ;
    const size_t vb = (size_t)h * SQ * HD;

    auto issue = [&](int s, int k0) {
        const uint32_t bufb = sb + (uint32_t)s * AV_BUF;
#pragma unroll
        for (int it = 0; it < 16; it++) {
            int c = tid + it * 256;
            int op = c >> 11;
            int cc = c & 2047;
            int row = cc >> 4;
            int ch  = cc & 15;
            const __half* p = op ? AwL : AwH;
            const void* g = p + wb + (size_t)row * SQ + k0 + ch * 8;
            uint32_t d = bufb + (op ? AV_WL : AV_WH) + (uint32_t)(ch >> 3) * 16384
                         + sw(row * 128 + (ch & 7) * 16);
            asm volatile("cp.async.cg.shared.global [%0], [%1], 16;\n"
                         :: "r"(d), "l"(g));
        }
#pragma unroll
        for (int it = 0; it < 8; it++) {
            int c = tid + it * 256;
            int op = c >> 10;
            int cc = c & 1023;
            int row = cc >> 3;
            int ch  = cc & 7;
            const __half* p = op ? VsL : VsH;
            const void* g = p + vb + (size_t)(k0 + row) * HD + ch * 8;
            uint32_t d = bufb + (op ? AV_VL : AV_VH) + sw(row * 128 + ch * 16);
            asm volatile("cp.async.cg.shared.global [%0], [%1], 16;\n"
                         :: "r"(d), "l"(g));
        }
        asm volatile("cp.async.commit_group;\n" ::: "memory");
    };

    float acc[4][2][4] = {};
    const int NT = qt + 1;
    issue(0, 0);

    for (int i = 0; i < NT; i++) {
        if (i + 1 < NT) {
            issue((i + 1) & 1, (i + 1) * 128);
            asm volatile("cp.async.wait_group 1;\n" ::: "memory");
        } else {
            asm volatile("cp.async.wait_group 0;\n" ::: "memory");
        }
        __syncthreads();

        const uint32_t bufb = sb + (uint32_t)(i & 1) * AV_BUF;
#pragma unroll
        for (int ks = 0; ks < 8; ks++) {
            int half_ = ks >> 2, ksl = ks & 3;
            uint32_t ah[4][4], al[4][4];
#pragma unroll
            for (int mt = 0; mt < 4; mt++) {
                int rowq = wm * 64 + mt * 16 + (l & 15);
                int chk = ksl * 2 + (l >> 4);
                uint32_t off = sw(rowq * 128 + chk * 16);
                ldsm4(ah[mt], bufb + AV_WH + half_ * 16384 + off);
                ldsm4(al[mt], bufb + AV_WL + half_ * 16384 + off);
            }
            uint32_t bh[4], bl[4];
            {
                int rowk = ks * 16 + (l & 15);
                int colb = wn * 32 + (l >> 4) * 16;
                uint32_t off = sw(rowk * 128 + colb);
                ldsm4t(bh, bufb + AV_VH + off);
                ldsm4t(bl, bufb + AV_VL + off);
            }
#pragma unroll
            for (int mt = 0; mt < 4; mt++)
#pragma unroll
                for (int nt = 0; nt < 2; nt++) {
                    mma16816(acc[mt][nt], ah[mt], bh + 2 * nt);
                    mma16816(acc[mt][nt], ah[mt], bl + 2 * nt);
                    mma16816(acc[mt][nt], al[mt], bh + 2 * nt);
                }
        }
        __syncthreads();
    }

#pragma unroll
    for (int mt = 0; mt < 4; mt++)
#pragma unroll
        for (int nt = 0; nt < 2; nt++)
#pragma unroll
            for (int hf = 0; hf < 2; hf++) {
                int q = q0 + wm * 64 + mt * 16 + (l >> 2) + hf * 8;
                int d = wn * 16 + nt * 8 + (l & 3) * 2;
                float v0 = acc[mt][nt][hf * 2 + 0];
                float v1 = acc[mt][nt][hf * 2 + 1];
                __half h0 = __float2half_rn(v0);
                __half h1 = __float2half_rn(v1);
                __half l0 = __float2half_rn(v0 - __half2float(h0));
                __half l1 = __float2half_rn(v1 - __half2float(h1));
                size_t idx = (size_t)q * EM + h * HD + d;
                __half2 hp; hp.x = h0; hp.y = h1;
                __half2 lp; lp.x = l0; lp.y = l1;
                *(__half2*)(ctxH + idx) = hp;
                *(__half2*)(ctxL + idx) = lp;
            }
}

// ============================================================================
extern "C" void kernel_launch(void* const* d_in, const int* in_sizes, int n_in,
                              void* d_out, int out_size)
{
    const float* hid = (const float*)d_in[0];
    const float* Wq = (const float*)d_in[2];
    const float* bq = (const float*)d_in[3];
    const float* Wk = (const float*)d_in[4];
    const float* bk = (const float*)d_in[5];
    const float* Wv = (const float*)d_in[6];
    const float* bv = (const float*)d_in[7];
    const float* Wo = (const float*)d_in[8];
    const float* bo = (const float*)d_in[9];
    float* out = (float*)d_out;

    float *gq, *gk, *gv, *gsc;
    cudaGetSymbolAddress((void**)&gq,  g_Q);
    cudaGetSymbolAddress((void**)&gk,  g_K);
    cudaGetSymbolAddress((void**)&gv,  g_V);
    cudaGetSymbolAddress((void**)&gsc, g_scores);

    __half *hH, *hL, *qH, *qL, *kH, *kL, *vH, *vL, *oH, *oL, *cH, *cL;
    __half *QsH, *QsL, *KsH, *KsL, *VsH, *VsL, *AwH, *AwL;
    cudaGetSymbolAddress((void**)&hH, g_hidH); cudaGetSymbolAddress((void**)&hL, g_hidL);
    cudaGetSymbolAddress((void**)&qH, g_WqH);  cudaGetSymbolAddress((void**)&qL, g_WqL);
    cudaGetSymbolAddress((void**)&kH, g_WkH);  cudaGetSymbolAddress((void**)&kL, g_WkL);
    cudaGetSymbolAddress((void**)&vH, g_WvH);  cudaGetSymbolAddress((void**)&vL, g_WvL);
    cudaGetSymbolAddress((void**)&oH, g_WoH);  cudaGetSymbolAddress((void**)&oL, g_WoL);
    cudaGetSymbolAddress((void**)&cH, g_ctxH); cudaGetSymbolAddress((void**)&cL, g_ctxL);
    cudaGetSymbolAddress((void**)&QsH, g_QsH); cudaGetSymbolAddress((void**)&QsL, g_QsL);
    cudaGetSymbolAddress((void**)&KsH, g_KsH); cudaGetSymbolAddress((void**)&KsL, g_KsL);
    cudaGetSymbolAddress((void**)&VsH, g_VsH); cudaGetSymbolAddress((void**)&VsL, g_VsL);
    cudaGetSymbolAddress((void**)&AwH, g_AwH); cudaGetSymbolAddress((void**)&AwL, g_AwL);

    cudaFuncSetAttribute(mma_gemm<0, false, 2>, cudaFuncAttributeMaxDynamicSharedMemorySize, SMEM_SZ);
    cudaFuncSetAttribute(mma_gemm<1, true, 3>,  cudaFuncAttributeMaxDynamicSharedMemorySize, SMEM_SZ);
    cudaFuncSetAttribute(mma_gemm<1, true, 2>,  cudaFuncAttributeMaxDynamicSharedMemorySize, SMEM_SZ);
    cudaFuncSetAttribute(scores_mma, cudaFuncAttributeMaxDynamicSharedMemorySize, SC_SMEM);
    cudaFuncSetAttribute(attn_v_mma, cudaFuncAttributeMaxDynamicSharedMemorySize, AV_SMEM);

    const size_t n_attn = (size_t)SQ * EM;
    const size_t n_w    = (size_t)NH * SQ * SQ;
    const size_t n_kv   = (size_t)NH * SQ * HD;
    const bool has_w  = (size_t)out_size >= n_attn + n_w;
    const bool has_kv = (size_t)out_size >= n_attn + n_w + 2 * n_kv;
    float* scores = has_w ? (out + n_attn) : gsc;

    const int NCV = SQ * EM;
    split_f16<<<2048, 256>>>(hid, hH, hL, NCV);
    split_f16<<<2048, 256>>>(Wq,  qH, qL, NCV);
    split_f16<<<2048, 256>>>(Wk,  kH, kL, NCV);
    split_f16<<<2048, 256>>>(Wv,  vH, vL, NCV);
    split_f16<<<2048, 256>>>(Wo,  oH, oL, NCV);

    dim3 g16(16, 16), blk(256);
    // Q/K: 3-product (weights-path accuracy). V: 2-product (output-path only).
    mma_gemm<1, true, 3><<<g16, blk, SMEM_SZ>>>(hH, hL, qH, qL, bq, gq, QsH, QsL, 0.125f);
    mma_gemm<1, true, 3><<<g16, blk, SMEM_SZ>>>(hH, hL, kH, kL, bk, gk, KsH, KsL, 1.0f);
    mma_gemm<1, true, 2><<<g16, blk, SMEM_SZ>>>(hH, hL, vH, vH, bv, gv, VsH, VsL, 1.0f);

    scores_mma<<<dim3(16, 16, NH), blk, SC_SMEM>>>(QsH, QsL, KsH, KsL, scores);
    softmax_causal<<<dim3(SQ, NH), blk>>>(scores, AwH, AwL);
    attn_v_mma<<<dim3(16, NH), blk, AV_SMEM>>>(AwH, AwL, VsH, VsL, cH, cL);

    // out-proj: 2-product, ctx split produced directly by attn_v epilogue
    mma_gemm<0, false, 2><<<g16, blk, SMEM_SZ>>>(cH, cL, oH, oH, bo, out,
                                                 nullptr, nullptr, 1.0f);

    if (has_kv) {
        cudaMemcpyAsync(out + n_attn + n_w, gk, n_kv * sizeof(float),
                        cudaMemcpyDeviceToDevice);
        cudaMemcpyAsync(out + n_attn + n_w + n_kv, gv, n_kv * sizeof(float),
                        cudaMemcpyDeviceToDevice);
    }
}